// round 10
// baseline (speedup 1.0000x reference)
#include <cuda_runtime.h>
#include <math.h>

#define BB    32
#define NN    1000
#define FF    128
#define NODES 32000
#define MAXD  128
#define INF_F __int_as_float(0x7f800000)

// ---------------- scratch ----------------
__device__ unsigned short g_nbr[(size_t)NODES * MAXD];
__device__ int            g_deg[NODES];
__device__ float          g_m[NODES];     // current mask (0/1)
__device__ float          g_D[NODES];     // D_i = (deg_hat + 1e-5)^-0.5
__device__ float          g_w[NODES];     // gather weight (0 if invalid/dropped)
__device__ float          g_y[NODES];     // pooling scores
__device__ float          g_hA[(size_t)NODES * FF];
__device__ float          g_hB[(size_t)NODES * FF];
__device__ float          g_Wt[3 * FF * FF];          // Wt[l][k*128 + t] = W_l[t][k]
__device__ int            g_vlist[2 * NODES];         // compacted valid node ids per pool
__device__ int            g_bcnt[2 * BB];             // per-batch valid counts per pool

// ---------------- init: mask copy, weight transpose ----------------
__global__ void k_init(const float* __restrict__ mask,
                       const float* __restrict__ W0,
                       const float* __restrict__ W1,
                       const float* __restrict__ W2) {
    int idx = blockIdx.x * 256 + threadIdx.x;
    if (idx < NODES) g_m[idx] = mask[idx];
    if (idx < 3 * FF * FF) {
        int l = idx / (FF * FF);
        int r = idx - l * FF * FF;
        int k = r / FF;
        int t = r - k * FF;
        const float* W = (l == 0) ? W0 : ((l == 1) ? W1 : W2);
        g_Wt[idx] = W[t * FF + k];
    }
}

// ---------------- build adjacency lists + layer-0 D/w (A pre-masked) --------
__global__ void k_build(const float* __restrict__ A) {
    int row  = blockIdx.x * 8 + (threadIdx.x >> 5);
    int lane = threadIdx.x & 31;
    const float4* ar = (const float4*)(A + (size_t)row * NN);
    unsigned short* nb = g_nbr + (size_t)row * MAXD;
    int deg = 0;
    for (int base = 0; base < NN; base += 128) {
        int col = base + 4 * lane;
        float4 v = make_float4(0.f, 0.f, 0.f, 0.f);
        if (col < NN) v = __ldg(ar + (col >> 2));
        unsigned bits = (v.x != 0.f ? 1u : 0u) | (v.y != 0.f ? 2u : 0u)
                      | (v.z != 0.f ? 4u : 0u) | (v.w != 0.f ? 8u : 0u);
        int c = __popc(bits);
        int pre = c;
        #pragma unroll
        for (int off = 1; off < 32; off <<= 1) {
            int t = __shfl_up_sync(0xffffffffu, pre, off);
            if (lane >= off) pre += t;
        }
        int tot = __shfl_sync(0xffffffffu, pre, 31);
        int pos = deg + (pre - c);
        #pragma unroll
        for (int k = 0; k < 4; k++) {
            if (bits & (1u << k)) {
                if (pos < MAXD) nb[pos] = (unsigned short)(col + k);
                pos++;
            }
        }
        deg += tot;
    }
    if (lane == 0) {
        g_deg[row] = (deg < MAXD) ? deg : MAXD;
        // A pre-masked => row sum == deg exactly; s = 1 + deg (integer-exact)
        float s = (float)deg + 1.0f;
        float D = 1.0f / sqrtf(s + 1e-5f);
        g_D[row] = D;
        g_w[row] = g_m[row] * D;      // 0 for invalid nodes
    }
}

// ---------------- fused sparse L@x + Linear + ReLU (+ scores), compacted -----
__global__ void __launch_bounds__(256) k_gconv(
        const float* __restrict__ x_in, int in_sel, int out_sel,
        int layer, const float* __restrict__ bias, const float* __restrict__ p,
        const int* __restrict__ N_nodes, int slot) {
    __shared__ float sS[32 * 132];
    __shared__ int   sNode[32];

    int batch = blockIdx.x >> 5;
    int base  = (blockIdx.x & 31) * 32;
    int count = (slot < 0) ? N_nodes[batch] : g_bcnt[slot * BB + batch];
    if (base >= count) return;

    const float* in  = (in_sel == 0) ? x_in : ((in_sel == 1) ? g_hA : g_hB);
    float*       out = (out_sel == 1) ? g_hA : g_hB;

    int tid  = threadIdx.x;
    int wid  = tid >> 5, lane = tid & 31;
    int b1000 = batch * NN;
    const float4* in4 = (const float4*)in;

    if (tid < 32) {
        int pos = base + tid;
        int nd = -1;
        if (pos < count)
            nd = (slot < 0) ? (b1000 + pos) : g_vlist[slot * NODES + b1000 + pos];
        sNode[tid] = nd;
    }
    __syncthreads();

    // ---- Phase 1: gather (warp per node, 8-deep MLP) ----
    for (int q = 0; q < 4; q++) {
        int lr = wid * 4 + q;
        int node = sNode[lr];
        float4 a0 = make_float4(0.f, 0.f, 0.f, 0.f);
        float4 a1 = make_float4(0.f, 0.f, 0.f, 0.f);
        if (node >= 0) {
            float D  = g_D[node];
            float wi = g_w[node];
            float4 xv = in4[(size_t)node * 32 + lane];
            a0.x = wi * xv.x; a0.y = wi * xv.y; a0.z = wi * xv.z; a0.w = wi * xv.w;
            int deg = g_deg[node];
            const unsigned short* nb = g_nbr + (size_t)node * MAXD;
            for (int base2 = 0; base2 < deg; base2 += 32) {
                int lim = deg - base2; if (lim > 32) lim = 32;
                int myj = 0; float myw = 0.f;
                if (lane < lim) { myj = nb[base2 + lane]; myw = g_w[b1000 + myj]; }
                int t = 0;
                for (; t + 7 < lim; t += 8) {
                    int   j0 = __shfl_sync(0xffffffffu, myj, t);
                    int   j1 = __shfl_sync(0xffffffffu, myj, t + 1);
                    int   j2 = __shfl_sync(0xffffffffu, myj, t + 2);
                    int   j3 = __shfl_sync(0xffffffffu, myj, t + 3);
                    int   j4 = __shfl_sync(0xffffffffu, myj, t + 4);
                    int   j5 = __shfl_sync(0xffffffffu, myj, t + 5);
                    int   j6 = __shfl_sync(0xffffffffu, myj, t + 6);
                    int   j7 = __shfl_sync(0xffffffffu, myj, t + 7);
                    float w0 = __shfl_sync(0xffffffffu, myw, t);
                    float w1 = __shfl_sync(0xffffffffu, myw, t + 1);
                    float w2 = __shfl_sync(0xffffffffu, myw, t + 2);
                    float w3 = __shfl_sync(0xffffffffu, myw, t + 3);
                    float w4 = __shfl_sync(0xffffffffu, myw, t + 4);
                    float w5 = __shfl_sync(0xffffffffu, myw, t + 5);
                    float w6 = __shfl_sync(0xffffffffu, myw, t + 6);
                    float w7 = __shfl_sync(0xffffffffu, myw, t + 7);
                    float4 v0 = in4[(size_t)(b1000 + j0) * 32 + lane];
                    float4 v1 = in4[(size_t)(b1000 + j1) * 32 + lane];
                    float4 v2 = in4[(size_t)(b1000 + j2) * 32 + lane];
                    float4 v3 = in4[(size_t)(b1000 + j3) * 32 + lane];
                    float4 v4 = in4[(size_t)(b1000 + j4) * 32 + lane];
                    float4 v5 = in4[(size_t)(b1000 + j5) * 32 + lane];
                    float4 v6 = in4[(size_t)(b1000 + j6) * 32 + lane];
                    float4 v7 = in4[(size_t)(b1000 + j7) * 32 + lane];
                    a0.x += w0 * v0.x; a0.y += w0 * v0.y; a0.z += w0 * v0.z; a0.w += w0 * v0.w;
                    a1.x += w1 * v1.x; a1.y += w1 * v1.y; a1.z += w1 * v1.z; a1.w += w1 * v1.w;
                    a0.x += w2 * v2.x; a0.y += w2 * v2.y; a0.z += w2 * v2.z; a0.w += w2 * v2.w;
                    a1.x += w3 * v3.x; a1.y += w3 * v3.y; a1.z += w3 * v3.z; a1.w += w3 * v3.w;
                    a0.x += w4 * v4.x; a0.y += w4 * v4.y; a0.z += w4 * v4.z; a0.w += w4 * v4.w;
                    a1.x += w5 * v5.x; a1.y += w5 * v5.y; a1.z += w5 * v5.z; a1.w += w5 * v5.w;
                    a0.x += w6 * v6.x; a0.y += w6 * v6.y; a0.z += w6 * v6.z; a0.w += w6 * v6.w;
                    a1.x += w7 * v7.x; a1.y += w7 * v7.y; a1.z += w7 * v7.z; a1.w += w7 * v7.w;
                }
                for (; t < lim; t++) {
                    int   j0 = __shfl_sync(0xffffffffu, myj, t);
                    float w0 = __shfl_sync(0xffffffffu, myw, t);
                    float4 v0 = in4[(size_t)(b1000 + j0) * 32 + lane];
                    a0.x += w0 * v0.x; a0.y += w0 * v0.y; a0.z += w0 * v0.z; a0.w += w0 * v0.w;
                }
            }
            a0.x = D * (a0.x + a1.x);
            a0.y = D * (a0.y + a1.y);
            a0.z = D * (a0.z + a1.z);
            a0.w = D * (a0.w + a1.w);
        }
        ((float4*)(sS + lr * 132))[lane] = a0;
    }
    __syncthreads();

    // ---- Phase 2: 32x128 GEMM; W rows from L1 ----
    int tx = tid & 31, ty = tid >> 5;
    const float4* W4 = (const float4*)(g_Wt + layer * FF * FF);
    float acc[4][4];
    #pragma unroll
    for (int j = 0; j < 4; j++)
        #pragma unroll
        for (int c = 0; c < 4; c++) acc[j][c] = 0.0f;

    #pragma unroll 8
    for (int kk = 0; kk < FF; kk += 4) {
        float4 b0 = *(const float4*)&sS[(ty * 4 + 0) * 132 + kk];
        float4 b1 = *(const float4*)&sS[(ty * 4 + 1) * 132 + kk];
        float4 b2 = *(const float4*)&sS[(ty * 4 + 2) * 132 + kk];
        float4 b3 = *(const float4*)&sS[(ty * 4 + 3) * 132 + kk];
        #pragma unroll
        for (int i = 0; i < 4; i++) {
            float4 wv = __ldg(W4 + (kk + i) * 32 + tx);
            float s0 = (i == 0) ? b0.x : (i == 1) ? b0.y : (i == 2) ? b0.z : b0.w;
            float s1 = (i == 0) ? b1.x : (i == 1) ? b1.y : (i == 2) ? b1.z : b1.w;
            float s2 = (i == 0) ? b2.x : (i == 1) ? b2.y : (i == 2) ? b2.z : b2.w;
            float s3 = (i == 0) ? b3.x : (i == 1) ? b3.y : (i == 2) ? b3.z : b3.w;
            acc[0][0] += s0 * wv.x; acc[0][1] += s0 * wv.y; acc[0][2] += s0 * wv.z; acc[0][3] += s0 * wv.w;
            acc[1][0] += s1 * wv.x; acc[1][1] += s1 * wv.y; acc[1][2] += s1 * wv.z; acc[1][3] += s1 * wv.w;
            acc[2][0] += s2 * wv.x; acc[2][1] += s2 * wv.y; acc[2][2] += s2 * wv.z; acc[2][3] += s2 * wv.w;
            acc[3][0] += s3 * wv.x; acc[3][1] += s3 * wv.y; acc[3][2] += s3 * wv.z; acc[3][3] += s3 * wv.w;
        }
    }

    float4 bias4 = __ldg((const float4*)bias + tx);
    float  s2p = 0.f;
    float4 pv  = make_float4(0.f, 0.f, 0.f, 0.f);
    if (p) {
        pv = __ldg((const float4*)p + tx);
        s2p = pv.x * pv.x + pv.y * pv.y + pv.z * pv.z + pv.w * pv.w;
        #pragma unroll
        for (int o = 16; o; o >>= 1) s2p += __shfl_xor_sync(0xffffffffu, s2p, o);
    }

    #pragma unroll
    for (int j = 0; j < 4; j++) {
        int node = sNode[ty * 4 + j];
        float4 o;
        o.x = fmaxf(acc[j][0] + bias4.x, 0.0f);
        o.y = fmaxf(acc[j][1] + bias4.y, 0.0f);
        o.z = fmaxf(acc[j][2] + bias4.z, 0.0f);
        o.w = fmaxf(acc[j][3] + bias4.w, 0.0f);
        if (node >= 0) {
            ((float4*)(out + (size_t)node * FF))[tx] = o;
            if (p) {
                float s1 = o.x * pv.x + o.y * pv.y + o.z * pv.z + o.w * pv.w;
                #pragma unroll
                for (int of = 16; of; of >>= 1) s1 += __shfl_xor_sync(0xffffffffu, s1, of);
                if (tx == 0) g_y[node] = s1 / sqrtf(s2p);
            }
        }
    }
}

// ---------------- rank: 8 blocks per batch, 125 nodes each ------------------
// grid = 32*8, block 1024. Thread t: node slice*125 + (t>>3), j-segment (t&7).
__global__ void __launch_bounds__(1024) k_rank(const int* __restrict__ N_nodes, int first) {
    __shared__ float key[NN];
    __shared__ int   part[125 * 8];
    int b     = blockIdx.x >> 3;
    int slice = blockIdx.x & 7;
    int t = threadIdx.x;

    if (t < NN) {
        int node = b * NN + t;
        key[t] = (g_m[node] > 0.f) ? g_y[node] : INF_F;
    }
    __syncthreads();
    int validFlag = (t < NN && key[t] < INF_F) ? 1 : 0;
    int V = __syncthreads_count(validFlag);

    int Nn  = N_nodes[b];
    int Nr1 = (int)((float)Nn * 0.2f);
    int Nr  = first ? Nr1 : (int)((float)(Nn - Nr1) * 0.2f);
    int slot = first ? 0 : 1;

    int nl = t >> 3;                 // local node 0..127 (125 active)
    if (nl < 125) {
        int i = slice * 125 + nl;
        float ki = key[i];
        int cnt = 0;
        if (ki < INF_F) {
            int j0 = (t & 7) * 125;
            #pragma unroll 5
            for (int j = j0; j < j0 + 125; j++) {
                float kj = key[j];
                cnt += (kj < ki) || (kj == ki && j < i);   // stable ascending rank
            }
        }
        part[nl * 8 + (t & 7)] = cnt;
    }
    __syncthreads();

    if (t < 125) {
        int i = slice * 125 + t;
        int node = b * NN + i;
        if (key[i] < INF_F) {
            int c = 0;
            #pragma unroll
            for (int r = 0; r < 8; r++) c += part[t * 8 + r];
            bool keep = (c >= Nr);
            g_m[node] = keep ? 1.0f : 0.0f;
            if (keep) g_vlist[slot * NODES + b * NN + (c - Nr)] = node;
            else      g_w[node] = 0.0f;
        }
        // never-valid nodes: g_m, g_w already 0
    }
    if (slice == 0 && t == 0) g_bcnt[slot * BB + b] = V - Nr;
}

// ---------------- degD/w recompute from new mask (high grid, exact) ---------
__global__ void k_degw() {
    int node = blockIdx.x * 256 + threadIdx.x;
    if (node >= NODES) return;
    if (g_m[node] <= 0.f) return;             // dropped w already zeroed by k_rank
    int b1000 = (node / NN) * NN;
    int deg = g_deg[node];
    const unsigned short* nb = g_nbr + (size_t)node * MAXD;
    float s = 1.0f;                            // self loop; adds of 0/1 — exact
    #pragma unroll 4
    for (int k = 0; k < deg; k++) s += g_m[b1000 + nb[k]];
    float D = 1.0f / sqrtf(s + 1e-5f);
    g_D[node] = D;
    g_w[node] = D * tanhf(g_y[node]);
}

// ---------------- global max pool + FC (mask-guarded vs stale rows) ----------
__global__ void k_final(const float* __restrict__ Wfc, const float* __restrict__ bfc,
                        float* __restrict__ outp) {
    __shared__ float red[8][FF];
    __shared__ float gmx[FF];
    int b = blockIdx.x;
    int f = threadIdx.x & 127;
    int g = threadIdx.x >> 7;
    const float* hb = g_hA + (size_t)b * NN * FF + f;
    const float* mb = g_m + b * NN;
    float mx = 0.0f;
    #pragma unroll 5
    for (int i = g * 125; i < (g + 1) * 125; i++)
        mx = fmaxf(mx, hb[(size_t)i * FF] * mb[i]);
    red[g][f] = mx;
    __syncthreads();
    if (threadIdx.x < FF) {
        float m = red[0][f];
        #pragma unroll
        for (int r = 1; r < 8; r++) m = fmaxf(m, red[r][f]);
        gmx[f] = m;
    }
    __syncthreads();
    if (threadIdx.x < 64) {
        float s = bfc[threadIdx.x];
        #pragma unroll 4
        for (int k = 0; k < FF; k++) s += gmx[k] * Wfc[threadIdx.x * FF + k];
        outp[b * 64 + threadIdx.x] = s;
    }
}

// ---------------- launch ----------------
extern "C" void kernel_launch(void* const* d_in, const int* in_sizes, int n_in,
                              void* d_out, int out_size) {
    const float* x    = (const float*)d_in[0];
    const float* A    = (const float*)d_in[1];
    const float* mask = (const float*)d_in[2];
    const int*   Nn   = (const int*)d_in[3];
    const float* W0   = (const float*)d_in[4];
    const float* b0   = (const float*)d_in[5];
    const float* W1   = (const float*)d_in[6];
    const float* b1   = (const float*)d_in[7];
    const float* W2   = (const float*)d_in[8];
    const float* b2   = (const float*)d_in[9];
    const float* p0   = (const float*)d_in[10];
    const float* p1   = (const float*)d_in[11];
    const float* Wfc  = (const float*)d_in[12];
    const float* bfc  = (const float*)d_in[13];
    float* outp = (float*)d_out;

    k_init <<<192, 256>>>(mask, W0, W1, W2);
    k_build<<<4000, 256>>>(A);

    // layer 0: x -> hA (identity valid list)
    k_gconv<<<1024, 256>>>(x, 0, 1, 0, b0, p0, Nn, -1);
    k_rank <<<256, 1024>>>(Nn, 1);
    k_degw <<<125, 256>>>();

    // layer 1: hA -> hB (compacted slot 0)
    k_gconv<<<1024, 256>>>(x, 1, 2, 1, b1, p1, Nn, 0);
    k_rank <<<256, 1024>>>(Nn, 0);
    k_degw <<<125, 256>>>();

    // layer 2: hB -> hA (compacted slot 1)
    k_gconv<<<1024, 256>>>(x, 2, 1, 2, b2, (const float*)0, Nn, 1);

    k_final<<<32, 1024>>>(Wfc, bfc, outp);
}

// round 12
// speedup vs baseline: 1.4429x; 1.4429x over previous
#include <cuda_runtime.h>
#include <math.h>

#define BB    32
#define NN    1000
#define FF    128
#define NODES 32000
#define MAXD  128
#define INF_F __int_as_float(0x7f800000)

// ---------------- scratch ----------------
__device__ unsigned short g_nbr[(size_t)NODES * MAXD];
__device__ int            g_deg[NODES];
__device__ float          g_m[NODES];     // current mask (0/1)
__device__ float          g_mn[NODES];    // next mask (double buffer; no races)
__device__ float          g_D[NODES];     // D_i = (deg_hat + 1e-5)^-0.5
__device__ float          g_w[NODES];     // gather weight (0 if invalid/dropped)
__device__ float          g_y[NODES];     // pooling scores
__device__ float          g_hA[(size_t)NODES * FF];
__device__ float          g_hB[(size_t)NODES * FF];
__device__ float          g_Wt[3 * FF * FF];          // Wt[l][k*128 + t] = W_l[t][k]
__device__ int            g_vlist[2 * NODES];         // compacted valid node ids per pool
__device__ int            g_bcnt[2 * BB];             // per-batch valid counts per pool

// ---------------- init: mask copy, weight transpose ----------------
__global__ void k_init(const float* __restrict__ mask,
                       const float* __restrict__ W0,
                       const float* __restrict__ W1,
                       const float* __restrict__ W2) {
    int idx = blockIdx.x * 256 + threadIdx.x;
    if (idx < NODES) g_m[idx] = mask[idx];
    if (idx < 3 * FF * FF) {
        int l = idx / (FF * FF);
        int r = idx - l * FF * FF;
        int k = r / FF;
        int t = r - k * FF;
        const float* W = (l == 0) ? W0 : ((l == 1) ? W1 : W2);
        g_Wt[idx] = W[t * FF + k];
    }
}

// ---------------- build adjacency lists + layer-0 D/w (A pre-masked) --------
__global__ void k_build(const float* __restrict__ A) {
    int row  = blockIdx.x * 8 + (threadIdx.x >> 5);
    int lane = threadIdx.x & 31;
    const float4* ar = (const float4*)(A + (size_t)row * NN);
    unsigned short* nb = g_nbr + (size_t)row * MAXD;
    int deg = 0;
    for (int base = 0; base < NN; base += 128) {
        int col = base + 4 * lane;
        float4 v = make_float4(0.f, 0.f, 0.f, 0.f);
        if (col < NN) v = __ldg(ar + (col >> 2));
        unsigned bits = (v.x != 0.f ? 1u : 0u) | (v.y != 0.f ? 2u : 0u)
                      | (v.z != 0.f ? 4u : 0u) | (v.w != 0.f ? 8u : 0u);
        int c = __popc(bits);
        int pre = c;
        #pragma unroll
        for (int off = 1; off < 32; off <<= 1) {
            int t = __shfl_up_sync(0xffffffffu, pre, off);
            if (lane >= off) pre += t;
        }
        int tot = __shfl_sync(0xffffffffu, pre, 31);
        int pos = deg + (pre - c);
        #pragma unroll
        for (int k = 0; k < 4; k++) {
            if (bits & (1u << k)) {
                if (pos < MAXD) nb[pos] = (unsigned short)(col + k);
                pos++;
            }
        }
        deg += tot;
    }
    if (lane == 0) {
        g_deg[row] = (deg < MAXD) ? deg : MAXD;
        float s = (float)deg + 1.0f;              // A pre-masked: row sum == deg
        float D = 1.0f / sqrtf(s + 1e-5f);
        g_D[row] = D;
        g_w[row] = g_m[row] * D;                  // 0 for invalid nodes
    }
}

// ---------------- fused sparse L@x + Linear + ReLU (+ scores), compacted -----
__global__ void __launch_bounds__(256) k_gconv(
        const float* __restrict__ x_in, int in_sel, int out_sel,
        int layer, const float* __restrict__ bias, const float* __restrict__ p,
        const int* __restrict__ N_nodes, int slot) {
    __shared__ float sS[32 * 132];
    __shared__ int   sNode[32];

    int batch = blockIdx.x >> 5;
    int base  = (blockIdx.x & 31) * 32;
    int count = (slot < 0) ? N_nodes[batch] : g_bcnt[slot * BB + batch];
    if (base >= count) return;

    const float* in  = (in_sel == 0) ? x_in : ((in_sel == 1) ? g_hA : g_hB);
    float*       out = (out_sel == 1) ? g_hA : g_hB;

    int tid  = threadIdx.x;
    int wid  = tid >> 5, lane = tid & 31;
    int b1000 = batch * NN;
    const float4* in4 = (const float4*)in;

    if (tid < 32) {
        int pos = base + tid;
        int nd = -1;
        if (pos < count)
            nd = (slot < 0) ? (b1000 + pos) : g_vlist[slot * NODES + b1000 + pos];
        sNode[tid] = nd;
    }
    __syncthreads();

    // ---- Phase 1: gather (warp per node, 8-deep MLP) ----
    for (int q = 0; q < 4; q++) {
        int lr = wid * 4 + q;
        int node = sNode[lr];
        float4 a0 = make_float4(0.f, 0.f, 0.f, 0.f);
        float4 a1 = make_float4(0.f, 0.f, 0.f, 0.f);
        if (node >= 0) {
            float D  = g_D[node];
            float wi = g_w[node];
            float4 xv = in4[(size_t)node * 32 + lane];
            a0.x = wi * xv.x; a0.y = wi * xv.y; a0.z = wi * xv.z; a0.w = wi * xv.w;
            int deg = g_deg[node];
            const unsigned short* nb = g_nbr + (size_t)node * MAXD;
            for (int base2 = 0; base2 < deg; base2 += 32) {
                int lim = deg - base2; if (lim > 32) lim = 32;
                int myj = 0; float myw = 0.f;
                if (lane < lim) { myj = nb[base2 + lane]; myw = g_w[b1000 + myj]; }
                int t = 0;
                for (; t + 7 < lim; t += 8) {
                    int   j0 = __shfl_sync(0xffffffffu, myj, t);
                    int   j1 = __shfl_sync(0xffffffffu, myj, t + 1);
                    int   j2 = __shfl_sync(0xffffffffu, myj, t + 2);
                    int   j3 = __shfl_sync(0xffffffffu, myj, t + 3);
                    int   j4 = __shfl_sync(0xffffffffu, myj, t + 4);
                    int   j5 = __shfl_sync(0xffffffffu, myj, t + 5);
                    int   j6 = __shfl_sync(0xffffffffu, myj, t + 6);
                    int   j7 = __shfl_sync(0xffffffffu, myj, t + 7);
                    float w0 = __shfl_sync(0xffffffffu, myw, t);
                    float w1 = __shfl_sync(0xffffffffu, myw, t + 1);
                    float w2 = __shfl_sync(0xffffffffu, myw, t + 2);
                    float w3 = __shfl_sync(0xffffffffu, myw, t + 3);
                    float w4 = __shfl_sync(0xffffffffu, myw, t + 4);
                    float w5 = __shfl_sync(0xffffffffu, myw, t + 5);
                    float w6 = __shfl_sync(0xffffffffu, myw, t + 6);
                    float w7 = __shfl_sync(0xffffffffu, myw, t + 7);
                    float4 v0 = in4[(size_t)(b1000 + j0) * 32 + lane];
                    float4 v1 = in4[(size_t)(b1000 + j1) * 32 + lane];
                    float4 v2 = in4[(size_t)(b1000 + j2) * 32 + lane];
                    float4 v3 = in4[(size_t)(b1000 + j3) * 32 + lane];
                    float4 v4 = in4[(size_t)(b1000 + j4) * 32 + lane];
                    float4 v5 = in4[(size_t)(b1000 + j5) * 32 + lane];
                    float4 v6 = in4[(size_t)(b1000 + j6) * 32 + lane];
                    float4 v7 = in4[(size_t)(b1000 + j7) * 32 + lane];
                    a0.x += w0 * v0.x; a0.y += w0 * v0.y; a0.z += w0 * v0.z; a0.w += w0 * v0.w;
                    a1.x += w1 * v1.x; a1.y += w1 * v1.y; a1.z += w1 * v1.z; a1.w += w1 * v1.w;
                    a0.x += w2 * v2.x; a0.y += w2 * v2.y; a0.z += w2 * v2.z; a0.w += w2 * v2.w;
                    a1.x += w3 * v3.x; a1.y += w3 * v3.y; a1.z += w3 * v3.z; a1.w += w3 * v3.w;
                    a0.x += w4 * v4.x; a0.y += w4 * v4.y; a0.z += w4 * v4.z; a0.w += w4 * v4.w;
                    a1.x += w5 * v5.x; a1.y += w5 * v5.y; a1.z += w5 * v5.z; a1.w += w5 * v5.w;
                    a0.x += w6 * v6.x; a0.y += w6 * v6.y; a0.z += w6 * v6.z; a0.w += w6 * v6.w;
                    a1.x += w7 * v7.x; a1.y += w7 * v7.y; a1.z += w7 * v7.z; a1.w += w7 * v7.w;
                }
                for (; t < lim; t++) {
                    int   j0 = __shfl_sync(0xffffffffu, myj, t);
                    float w0 = __shfl_sync(0xffffffffu, myw, t);
                    float4 v0 = in4[(size_t)(b1000 + j0) * 32 + lane];
                    a0.x += w0 * v0.x; a0.y += w0 * v0.y; a0.z += w0 * v0.z; a0.w += w0 * v0.w;
                }
            }
            a0.x = D * (a0.x + a1.x);
            a0.y = D * (a0.y + a1.y);
            a0.z = D * (a0.z + a1.z);
            a0.w = D * (a0.w + a1.w);
        }
        ((float4*)(sS + lr * 132))[lane] = a0;
    }
    __syncthreads();

    // ---- Phase 2: 32x128 GEMM; W rows from L1 ----
    int tx = tid & 31, ty = tid >> 5;
    const float4* W4 = (const float4*)(g_Wt + layer * FF * FF);
    float acc[4][4];
    #pragma unroll
    for (int j = 0; j < 4; j++)
        #pragma unroll
        for (int c = 0; c < 4; c++) acc[j][c] = 0.0f;

    #pragma unroll 8
    for (int kk = 0; kk < FF; kk += 4) {
        float4 b0 = *(const float4*)&sS[(ty * 4 + 0) * 132 + kk];
        float4 b1 = *(const float4*)&sS[(ty * 4 + 1) * 132 + kk];
        float4 b2 = *(const float4*)&sS[(ty * 4 + 2) * 132 + kk];
        float4 b3 = *(const float4*)&sS[(ty * 4 + 3) * 132 + kk];
        #pragma unroll
        for (int i = 0; i < 4; i++) {
            float4 wv = __ldg(W4 + (kk + i) * 32 + tx);
            float s0 = (i == 0) ? b0.x : (i == 1) ? b0.y : (i == 2) ? b0.z : b0.w;
            float s1 = (i == 0) ? b1.x : (i == 1) ? b1.y : (i == 2) ? b1.z : b1.w;
            float s2 = (i == 0) ? b2.x : (i == 1) ? b2.y : (i == 2) ? b2.z : b2.w;
            float s3 = (i == 0) ? b3.x : (i == 1) ? b3.y : (i == 2) ? b3.z : b3.w;
            acc[0][0] += s0 * wv.x; acc[0][1] += s0 * wv.y; acc[0][2] += s0 * wv.z; acc[0][3] += s0 * wv.w;
            acc[1][0] += s1 * wv.x; acc[1][1] += s1 * wv.y; acc[1][2] += s1 * wv.z; acc[1][3] += s1 * wv.w;
            acc[2][0] += s2 * wv.x; acc[2][1] += s2 * wv.y; acc[2][2] += s2 * wv.z; acc[2][3] += s2 * wv.w;
            acc[3][0] += s3 * wv.x; acc[3][1] += s3 * wv.y; acc[3][2] += s3 * wv.z; acc[3][3] += s3 * wv.w;
        }
    }

    float4 bias4 = __ldg((const float4*)bias + tx);
    float  s2p = 0.f;
    float4 pv  = make_float4(0.f, 0.f, 0.f, 0.f);
    if (p) {
        pv = __ldg((const float4*)p + tx);
        s2p = pv.x * pv.x + pv.y * pv.y + pv.z * pv.z + pv.w * pv.w;
        #pragma unroll
        for (int o = 16; o; o >>= 1) s2p += __shfl_xor_sync(0xffffffffu, s2p, o);
    }

    #pragma unroll
    for (int j = 0; j < 4; j++) {
        int node = sNode[ty * 4 + j];
        float4 o;
        o.x = fmaxf(acc[j][0] + bias4.x, 0.0f);
        o.y = fmaxf(acc[j][1] + bias4.y, 0.0f);
        o.z = fmaxf(acc[j][2] + bias4.z, 0.0f);
        o.w = fmaxf(acc[j][3] + bias4.w, 0.0f);
        if (node >= 0) {
            ((float4*)(out + (size_t)node * FF))[tx] = o;
            if (p) {
                float s1 = o.x * pv.x + o.y * pv.y + o.z * pv.z + o.w * pv.w;
                #pragma unroll
                for (int of = 16; of; of >>= 1) s1 += __shfl_xor_sync(0xffffffffu, s1, of);
                if (tx == 0) g_y[node] = s1 / sqrtf(s2p);
            }
        }
    }
}

// ---------------- rank: 8 blocks per batch; writes g_mn only (race-free) ----
__global__ void __launch_bounds__(1024) k_rank(const int* __restrict__ N_nodes, int first) {
    __shared__ float key[NN];
    __shared__ int   part[125 * 8];
    int b     = blockIdx.x >> 3;
    int slice = blockIdx.x & 7;
    int t = threadIdx.x;

    if (t < NN) {
        int node = b * NN + t;
        key[t] = (g_m[node] > 0.f) ? g_y[node] : INF_F;
    }
    __syncthreads();
    int validFlag = (t < NN && key[t] < INF_F) ? 1 : 0;
    int V = __syncthreads_count(validFlag);

    int Nn  = N_nodes[b];
    int Nr1 = (int)((float)Nn * 0.2f);
    int Nr  = first ? Nr1 : (int)((float)(Nn - Nr1) * 0.2f);
    int slot = first ? 0 : 1;

    int nl = t >> 3;                 // local node 0..127 (125 active)
    if (nl < 125) {
        int i = slice * 125 + nl;
        float ki = key[i];
        int cnt = 0;
        if (ki < INF_F) {
            int j0 = (t & 7) * 125;
            #pragma unroll 5
            for (int j = j0; j < j0 + 125; j++) {
                float kj = key[j];
                cnt += (kj < ki) || (kj == ki && j < i);   // stable ascending rank
            }
        }
        part[nl * 8 + (t & 7)] = cnt;
    }
    __syncthreads();

    if (t < 125) {
        int i = slice * 125 + t;
        int node = b * NN + i;
        if (key[i] < INF_F) {
            int c = 0;
            #pragma unroll
            for (int r = 0; r < 8; r++) c += part[t * 8 + r];
            bool keep = (c >= Nr);
            g_mn[node] = keep ? 1.0f : 0.0f;
            if (keep) g_vlist[slot * NODES + b * NN + (c - Nr)] = node;
        } else {
            g_mn[node] = 0.0f;
        }
    }
    if (slice == 0 && t == 0) g_bcnt[slot * BB + b] = V - Nr;
}

// ---------------- degw: warp-per-node, commit mask, compute D/w (exact) -----
__global__ void k_degw() {
    int node = blockIdx.x * 8 + (threadIdx.x >> 5);   // grid 4000
    int lane = threadIdx.x & 31;
    float mn = g_mn[node];
    if (lane == 0) g_m[node] = mn;                     // commit new mask
    if (mn > 0.f) {
        int b1000 = (node / NN) * NN;
        int deg = g_deg[node];
        const unsigned short* nb = g_nbr + (size_t)node * MAXD;
        float s = 0.f;                                 // 0/1 adds, sum <= 128: exact
        for (int k = lane; k < deg; k += 32) s += g_mn[b1000 + nb[k]];
        #pragma unroll
        for (int o = 16; o; o >>= 1) s += __shfl_xor_sync(0xffffffffu, s, o);
        if (lane == 0) {
            float D = 1.0f / sqrtf(s + 1.0f + 1e-5f);
            g_D[node] = D;
            g_w[node] = D * tanhf(g_y[node]);
        }
    } else if (lane == 0) {
        g_w[node] = 0.0f;
    }
}

// ---------------- global max pool + FC (mask-guarded vs stale rows) ----------
__global__ void k_final(const float* __restrict__ Wfc, const float* __restrict__ bfc,
                        float* __restrict__ outp) {
    __shared__ float red[8][FF];
    __shared__ float gmx[FF];
    int b = blockIdx.x;
    int f = threadIdx.x & 127;
    int g = threadIdx.x >> 7;
    const float* hb = g_hA + (size_t)b * NN * FF + f;
    const float* mb = g_m + b * NN;
    float mx = 0.0f;
    #pragma unroll 5
    for (int i = g * 125; i < (g + 1) * 125; i++)
        mx = fmaxf(mx, hb[(size_t)i * FF] * mb[i]);
    red[g][f] = mx;
    __syncthreads();
    if (threadIdx.x < FF) {
        float m = red[0][f];
        #pragma unroll
        for (int r = 1; r < 8; r++) m = fmaxf(m, red[r][f]);
        gmx[f] = m;
    }
    __syncthreads();
    if (threadIdx.x < 64) {
        float s = bfc[threadIdx.x];
        #pragma unroll 4
        for (int k = 0; k < FF; k++) s += gmx[k] * Wfc[threadIdx.x * FF + k];
        outp[b * 64 + threadIdx.x] = s;
    }
}

// ---------------- launch ----------------
extern "C" void kernel_launch(void* const* d_in, const int* in_sizes, int n_in,
                              void* d_out, int out_size) {
    const float* x    = (const float*)d_in[0];
    const float* A    = (const float*)d_in[1];
    const float* mask = (const float*)d_in[2];
    const int*   Nn   = (const int*)d_in[3];
    const float* W0   = (const float*)d_in[4];
    const float* b0   = (const float*)d_in[5];
    const float* W1   = (const float*)d_in[6];
    const float* b1   = (const float*)d_in[7];
    const float* W2   = (const float*)d_in[8];
    const float* b2   = (const float*)d_in[9];
    const float* p0   = (const float*)d_in[10];
    const float* p1   = (const float*)d_in[11];
    const float* Wfc  = (const float*)d_in[12];
    const float* bfc  = (const float*)d_in[13];
    float* outp = (float*)d_out;

    k_init <<<192, 256>>>(mask, W0, W1, W2);
    k_build<<<4000, 256>>>(A);

    // layer 0: x -> hA (identity valid list)
    k_gconv<<<1024, 256>>>(x, 0, 1, 0, b0, p0, Nn, -1);
    k_rank <<<256, 1024>>>(Nn, 1);
    k_degw <<<4000, 256>>>();

    // layer 1: hA -> hB (compacted slot 0)
    k_gconv<<<1024, 256>>>(x, 1, 2, 1, b1, p1, Nn, 0);
    k_rank <<<256, 1024>>>(Nn, 0);
    k_degw <<<4000, 256>>>();

    // layer 2: hB -> hA (compacted slot 1)
    k_gconv<<<1024, 256>>>(x, 2, 1, 2, b2, (const float*)0, Nn, 1);

    k_final<<<32, 1024>>>(Wfc, bfc, outp);
}